// round 14
// baseline (speedup 1.0000x reference)
#include <cuda_runtime.h>
#include <cuda_bf16.h>
#include <cuda_fp16.h>
#include <cstdint>

#define NUM_USERS 50000
#define NUM_ITEMS 20000
#define NUM_NODES 70000
#define FEAT_DIM 768
#define HID 128
#define N_EDGES 2000000
#define LN_EPS 1e-5f
#define ALPHA 0.25f
#define NUM_BLK 69   // ceil(70000/1024)

// bgemm tile constants
#define GSTAGES 3
#define TILE_ELEMS (128 * 40)
#define GSMEM_BYTES (GSTAGES * 2 * TILE_ELEMS * 2)   // 61440 B

// ---------------- scratch (static device globals; no allocation) ----------------
__device__ __nv_bfloat16 g_featb[(size_t)NUM_ITEMS * FEAT_DIM];
__device__ __nv_bfloat16 g_W1t[(size_t)512 * FEAT_DIM];   // [N=512][K=768]
__device__ __nv_bfloat16 g_W2t[(size_t)128 * 512];        // [N=128][K=512]
__device__ __nv_bfloat16 g_W3t[(size_t)128 * 128];        // [N=128][K=128]
__device__ float g_h1[(size_t)NUM_ITEMS * 512];
__device__ __nv_bfloat16 g_h1b[(size_t)NUM_ITEMS * 512];
__device__ float g_h2[(size_t)NUM_ITEMS * HID];
__device__ __nv_bfloat16 g_h2b[(size_t)NUM_ITEMS * HID];
__device__ float g_h3[(size_t)NUM_ITEMS * HID];
__device__ float g_xsum[(size_t)NUM_NODES * HID];          // running fp32 sum
__device__ __align__(16) __half g_xhA[(size_t)NUM_NODES * HID];  // fp16 ping
__device__ __align__(16) __half g_xhB[(size_t)NUM_NODES * HID];  // fp16 pong
__device__ int   g_cnt[NUM_NODES];
__device__ float g_dinv[NUM_NODES];
__device__ int   g_rowptr[NUM_NODES + 1];
__device__ int   g_cursor[NUM_NODES];
__device__ int2  g_cw[N_EDGES];                            // fused (col, w-bits)
__device__ int   g_bsum[NUM_BLK];
__device__ int   g_boff[128];

// ---------------- cp.async helpers ----------------
__device__ __forceinline__ void cp16(void* smem_dst, const void* gsrc, bool pred) {
    uint32_t d = (uint32_t)__cvta_generic_to_shared(smem_dst);
    int sz = pred ? 16 : 0;
    asm volatile("cp.async.cg.shared.global [%0], [%1], 16, %2;\n"
                 :: "r"(d), "l"(gsrc), "r"(sz));
}
__device__ __forceinline__ void cp_commit() {
    asm volatile("cp.async.commit_group;\n");
}
template <int N>
__device__ __forceinline__ void cp_wait() {
    asm volatile("cp.async.wait_group %0;\n" :: "n"(N));
}

// ---------------- CSR build ----------------
__global__ void k_zero_cnt() {
    int i = blockIdx.x * blockDim.x + threadIdx.x;
    if (i < NUM_NODES) g_cnt[i] = 0;
}

__global__ void k_count(const int* __restrict__ ei) {
    int e = blockIdx.x * blockDim.x + threadIdx.x;
    if (e < N_EDGES) atomicAdd(&g_cnt[ei[N_EDGES + e]], 1);
}

// partial block sums for the scan + dinv (fused: both only need g_cnt)
__global__ void k_partial() {
    __shared__ int sh[32];
    int tid = threadIdx.x;
    int i = blockIdx.x * 1024 + tid;
    int c = 0;
    if (i < NUM_NODES) {
        c = g_cnt[i];
        g_dinv[i] = (c > 0) ? rsqrtf((float)c) : 0.0f;
    }
    int s = c;
#pragma unroll
    for (int o = 16; o > 0; o >>= 1) s += __shfl_down_sync(0xffffffffu, s, o);
    if ((tid & 31) == 0) sh[tid >> 5] = s;
    __syncthreads();
    if (tid < 32) {
        int v = sh[tid];
#pragma unroll
        for (int o = 16; o > 0; o >>= 1) v += __shfl_down_sync(0xffffffffu, v, o);
        if (tid == 0) g_bsum[blockIdx.x] = v;
    }
}

__global__ void k_scanb() {
    __shared__ int s[128];
    int tid = threadIdx.x;
    int v = (tid < NUM_BLK) ? g_bsum[tid] : 0;
    s[tid] = v;
    __syncthreads();
    for (int off = 1; off < 128; off <<= 1) {
        int add = 0;
        if (tid >= off) add = s[tid - off];
        __syncthreads();
        if (tid >= off) s[tid] += add;
        __syncthreads();
    }
    g_boff[tid] = s[tid] - v;
}

__global__ void k_scatter() {
    __shared__ int s[1024];
    int tid = threadIdx.x;
    int i = blockIdx.x * 1024 + tid;
    int c = (i < NUM_NODES) ? g_cnt[i] : 0;
    s[tid] = c;
    __syncthreads();
    for (int off = 1; off < 1024; off <<= 1) {
        int add = 0;
        if (tid >= off) add = s[tid - off];
        __syncthreads();
        if (tid >= off) s[tid] += add;
        __syncthreads();
    }
    if (i < NUM_NODES) {
        int p = g_boff[blockIdx.x] + s[tid] - c;
        g_rowptr[i] = p;
        g_cursor[i] = p;
    }
    if (i == NUM_NODES - 1) g_rowptr[NUM_NODES] = N_EDGES;
}

__global__ void k_fill(const int* __restrict__ ei) {
    int e = blockIdx.x * blockDim.x + threadIdx.x;
    if (e < N_EDGES) {
        int s = ei[e];
        int d = ei[N_EDGES + e];
        int pos = atomicAdd(&g_cursor[d], 1);
        float w = g_dinv[s] * g_dinv[d];
        g_cw[pos] = make_int2(s, __float_as_int(w));
    }
}

// ---------------- conversions ----------------
__global__ void k_cvtA(const float* __restrict__ A) {
    int i = blockIdx.x * blockDim.x + threadIdx.x;
    const int total = NUM_ITEMS * FEAT_DIM / 4;
    if (i < total) {
        float4 v = ((const float4*)A)[i];
        __nv_bfloat162 p0 = __floats2bfloat162_rn(v.x, v.y);
        __nv_bfloat162 p1 = __floats2bfloat162_rn(v.z, v.w);
        uint2 u;
        u.x = *(unsigned int*)&p0;
        u.y = *(unsigned int*)&p1;
        ((uint2*)g_featb)[i] = u;
    }
}

__global__ void k_cvtWt(const float* __restrict__ W, __nv_bfloat16* __restrict__ Wt,
                        int K, int N) {
    __shared__ float sh[32][33];
    int k0 = blockIdx.y * 32, n0 = blockIdx.x * 32;
    int tx = threadIdx.x, ty = threadIdx.y;
    sh[ty][tx] = W[(size_t)(k0 + ty) * N + n0 + tx];
    __syncthreads();
    Wt[(size_t)(n0 + ty) * K + k0 + tx] = __float2bfloat16_rn(sh[tx][ty]);
}

// ---------------- bf16 tensor-core GEMM: 3-stage cp.async, 1 sync/iter, ldmatrix ----
// C = A @ Bt^T + bias.  A: [M][K] bf16, Bt: [N][K] bf16, C fp32 [M][N].
// BM=128, BN=128, BK=32.  256 threads, 8 warps as 4(m) x 2(n), warp tile 32x64.
// minblocks=3 caps regs at 85 -> 3 CTAs/SM (occupancy 34%).
__global__ __launch_bounds__(256, 3) void bgemm_bias(
    const __nv_bfloat16* __restrict__ A, const __nv_bfloat16* __restrict__ Bt,
    const float* __restrict__ bias, float* __restrict__ C, int M, int N, int K) {
    extern __shared__ __nv_bfloat16 sdyn[];
    __nv_bfloat16* Asb = sdyn;
    __nv_bfloat16* Bsb = sdyn + GSTAGES * TILE_ELEMS;
    int tid = threadIdx.x;
    int warp = tid >> 5, lane = tid & 31;
    int wm = (warp >> 1) * 32;
    int wn = (warp & 1) * 64;
    int bm = blockIdx.y * 128, bn = blockIdx.x * 128;
    int g = lane >> 2, tc = lane & 3;
    int lrow = lane & 7, lsel = lane >> 3;      // ldmatrix addressing

    float acc[2][8][4];
#pragma unroll
    for (int a = 0; a < 2; a++)
#pragma unroll
        for (int b = 0; b < 8; b++)
#pragma unroll
            for (int c = 0; c < 4; c++) acc[a][b][c] = 0.f;

    const int KT = K / 32;

    auto load_stage = [&](int k0, int s) {
        __nv_bfloat16* As = Asb + s * TILE_ELEMS;
        __nv_bfloat16* Bs = Bsb + s * TILE_ELEMS;
#pragma unroll
        for (int i = 0; i < 2; i++) {
            int c = tid + i * 256;
            int m = c >> 2;
            int kq = (c & 3) * 8;
            cp16(As + m * 40 + kq, A + (size_t)(bm + m) * K + k0 + kq, bm + m < M);
        }
#pragma unroll
        for (int i = 0; i < 2; i++) {
            int c = tid + i * 256;
            int n = c >> 2;
            int kq = (c & 3) * 8;
            cp16(Bs + n * 40 + kq, Bt + (size_t)(bn + n) * K + k0 + kq, true);
        }
    };

    load_stage(0, 0);
    cp_commit();
    if (KT > 1) load_stage(32, 1);
    cp_commit();

    int st = 0;
    for (int it = 0; it < KT; it++) {
        cp_wait<1>();
        __syncthreads();
        uint32_t asb = (uint32_t)__cvta_generic_to_shared(Asb + st * TILE_ELEMS);
        uint32_t bsb = (uint32_t)__cvta_generic_to_shared(Bsb + st * TILE_ELEMS);
#pragma unroll
        for (int ks = 0; ks < 2; ks++) {
            int kb = ks * 16;
            uint32_t af[2][4], bf[8][2];
#pragma unroll
            for (int mt = 0; mt < 2; mt++) {
                int row = wm + mt * 16 + lrow + ((lsel & 1) << 3);
                int col = kb + ((lsel >> 1) << 3);
                uint32_t addr = asb + (uint32_t)(row * 40 + col) * 2;
                asm volatile(
                    "ldmatrix.sync.aligned.m8n8.x4.shared.b16 {%0,%1,%2,%3}, [%4];\n"
                    : "=r"(af[mt][0]), "=r"(af[mt][1]), "=r"(af[mt][2]), "=r"(af[mt][3])
                    : "r"(addr));
            }
#pragma unroll
            for (int p = 0; p < 4; p++) {
                int row = wn + p * 16 + ((lsel >> 1) << 3) + lrow;
                int col = kb + ((lsel & 1) << 3);
                uint32_t addr = bsb + (uint32_t)(row * 40 + col) * 2;
                asm volatile(
                    "ldmatrix.sync.aligned.m8n8.x4.shared.b16 {%0,%1,%2,%3}, [%4];\n"
                    : "=r"(bf[2 * p][0]), "=r"(bf[2 * p][1]),
                      "=r"(bf[2 * p + 1][0]), "=r"(bf[2 * p + 1][1])
                    : "r"(addr));
            }
#pragma unroll
            for (int mt = 0; mt < 2; mt++)
#pragma unroll
                for (int nt = 0; nt < 8; nt++) {
                    asm volatile(
                        "mma.sync.aligned.m16n8k16.row.col.f32.bf16.bf16.f32 "
                        "{%0,%1,%2,%3}, {%4,%5,%6,%7}, {%8,%9}, {%0,%1,%2,%3};\n"
                        : "+f"(acc[mt][nt][0]), "+f"(acc[mt][nt][1]),
                          "+f"(acc[mt][nt][2]), "+f"(acc[mt][nt][3])
                        : "r"(af[mt][0]), "r"(af[mt][1]), "r"(af[mt][2]), "r"(af[mt][3]),
                          "r"(bf[nt][0]), "r"(bf[nt][1]));
                }
        }
        if (it + 2 < KT) {
            int ns = st + 2;
            if (ns >= GSTAGES) ns -= GSTAGES;
            load_stage((it + 2) * 32, ns);
        }
        cp_commit();
        if (++st == GSTAGES) st = 0;
    }
#pragma unroll
    for (int mt = 0; mt < 2; mt++) {
        int r0 = bm + wm + mt * 16 + g;
#pragma unroll
        for (int nt = 0; nt < 8; nt++) {
            int col = bn + wn + nt * 8 + 2 * tc;
            float bx = bias[col], by = bias[col + 1];
            if (r0 < M) {
                float2 v0 = make_float2(acc[mt][nt][0] + bx, acc[mt][nt][1] + by);
                *(float2*)(C + (size_t)r0 * N + col) = v0;
            }
            if (r0 + 8 < M) {
                float2 v1 = make_float2(acc[mt][nt][2] + bx, acc[mt][nt][3] + by);
                *(float2*)(C + (size_t)(r0 + 8) * N + col) = v1;
            }
        }
    }
}

// ---------------- LayerNorm + ReLU (fp32 in, bf16 out) ----------------
__global__ void ln_relu_512(const float* __restrict__ h, const float* __restrict__ g,
                            const float* __restrict__ be, __nv_bfloat16* __restrict__ hb) {
    __shared__ float sh1[8], sh2[8];
    int row = blockIdx.x;
    int tid = threadIdx.x;
    const float* r = h + (size_t)row * 512;
    float a = r[tid], b = r[tid + 256];
    float s = a + b, q = a * a + b * b;
#pragma unroll
    for (int o = 16; o > 0; o >>= 1) {
        s += __shfl_down_sync(0xffffffffu, s, o);
        q += __shfl_down_sync(0xffffffffu, q, o);
    }
    if ((tid & 31) == 0) { sh1[tid >> 5] = s; sh2[tid >> 5] = q; }
    __syncthreads();
    if (tid < 8) {
        s = sh1[tid]; q = sh2[tid];
#pragma unroll
        for (int o = 4; o > 0; o >>= 1) {
            s += __shfl_down_sync(0xffu, s, o);
            q += __shfl_down_sync(0xffu, q, o);
        }
        if (tid == 0) { sh1[0] = s; sh2[0] = q; }
    }
    __syncthreads();
    float mu = sh1[0] * (1.f / 512.f);
    float var = sh2[0] * (1.f / 512.f) - mu * mu;
    float inv = rsqrtf(var + LN_EPS);
    __nv_bfloat16* o = hb + (size_t)row * 512;
    o[tid] = __float2bfloat16_rn(fmaxf((a - mu) * inv * g[tid] + be[tid], 0.f));
    o[tid + 256] = __float2bfloat16_rn(fmaxf((b - mu) * inv * g[tid + 256] + be[tid + 256], 0.f));
}

// 2 rows per block (128 cols each)
__global__ void ln_relu_128(const float* __restrict__ h, const float* __restrict__ g,
                            const float* __restrict__ be, __nv_bfloat16* __restrict__ hb) {
    __shared__ float sh1[2][4], sh2[2][4];
    int half = threadIdx.x >> 7;
    int tid = threadIdx.x & 127;
    int row = blockIdx.x * 2 + half;
    const float* r = h + (size_t)row * 128;
    float a = r[tid];
    float s = a, q = a * a;
#pragma unroll
    for (int o = 16; o > 0; o >>= 1) {
        s += __shfl_down_sync(0xffffffffu, s, o);
        q += __shfl_down_sync(0xffffffffu, q, o);
    }
    if ((tid & 31) == 0) { sh1[half][tid >> 5] = s; sh2[half][tid >> 5] = q; }
    __syncthreads();
    float ts = sh1[half][0] + sh1[half][1] + sh1[half][2] + sh1[half][3];
    float tq = sh2[half][0] + sh2[half][1] + sh2[half][2] + sh2[half][3];
    float mu = ts * (1.f / 128.f);
    float var = tq * (1.f / 128.f) - mu * mu;
    float inv = rsqrtf(var + LN_EPS);
    hb[(size_t)row * 128 + tid] =
        __float2bfloat16_rn(fmaxf((a - mu) * inv * g[tid] + be[tid], 0.f));
}

// ---------------- fuse + user init: xsum = x0 (fp32), xhA = x0 (fp16) ----------------
__global__ void k_fuse(const float* __restrict__ emb, const float* __restrict__ mw) {
    __shared__ float sh[4];
    int row = blockIdx.x;
    int tid = threadIdx.x;
    float v = g_h3[(size_t)row * 128 + tid];
    float q = v * v;
#pragma unroll
    for (int o = 16; o > 0; o >>= 1) q += __shfl_down_sync(0xffffffffu, q, o);
    if ((tid & 31) == 0) sh[tid >> 5] = q;
    __syncthreads();
    if (tid == 0) sh[0] = sh[0] + sh[1] + sh[2] + sh[3];
    __syncthreads();
    float denom = fmaxf(sqrtf(sh[0]), 1e-12f);
    size_t gi = (size_t)(NUM_USERS + row) * 128 + tid;
    float e = emb[gi] + mw[0] * (v / denom);
    g_xsum[gi] = e;
    g_xhA[gi] = __float2half(e);
}

__global__ void k_user(const float* __restrict__ emb) {
    int i = blockIdx.x * blockDim.x + threadIdx.x;   // NUM_USERS*128/4 float4s
    const int total = NUM_USERS * HID / 4;
    if (i < total) {
        float4 v = ((const float4*)emb)[i];
        ((float4*)g_xsum)[i] = v;
        __half2 h0 = __floats2half2_rn(v.x, v.y);
        __half2 h1 = __floats2half2_rn(v.z, v.w);
        uint2 u;
        u.x = *(unsigned int*)&h0;
        u.y = *(unsigned int*)&h1;
        ((uint2*)g_xhA)[i] = u;
    }
}

// ---------------- pull-based propagation (fp16 gather, fp32 accumulate) ----------
// known-good shape: one warp per dst node, shfl staging, unroll 8.
__global__ void k_prop(const __half* __restrict__ xin, __half* __restrict__ xout,
                       float* __restrict__ out, int last) {
    int warp = (blockIdx.x * blockDim.x + threadIdx.x) >> 5;
    int lane = threadIdx.x & 31;
    if (warp >= NUM_NODES) return;
    int beg = g_rowptr[warp];
    int end = g_rowptr[warp + 1];
    float4 acc = make_float4(0.f, 0.f, 0.f, 0.f);
    int j = beg;
    for (; j + 32 <= end; j += 32) {
        int2 cw = g_cw[j + lane];
        int myc = cw.x;
        float myw = __int_as_float(cw.y);
#pragma unroll 8
        for (int k = 0; k < 32; k++) {
            int s = __shfl_sync(0xffffffffu, myc, k);
            float wv = __shfl_sync(0xffffffffu, myw, k);
            uint2 v = ((const uint2*)(xin + (size_t)s * 128))[lane];
            float2 f0 = __half22float2(*(__half2*)&v.x);
            float2 f1 = __half22float2(*(__half2*)&v.y);
            acc.x += wv * f0.x;
            acc.y += wv * f0.y;
            acc.z += wv * f1.x;
            acc.w += wv * f1.y;
        }
    }
    int n = end - j;
    if (n > 0) {
        int myc = 0;
        float myw = 0.f;
        if (lane < n) {
            int2 cw = g_cw[j + lane];
            myc = cw.x;
            myw = __int_as_float(cw.y);
        }
#pragma unroll 4
        for (int k = 0; k < n; k++) {
            int s = __shfl_sync(0xffffffffu, myc, k);
            float wv = __shfl_sync(0xffffffffu, myw, k);
            uint2 v = ((const uint2*)(xin + (size_t)s * 128))[lane];
            float2 f0 = __half22float2(*(__half2*)&v.x);
            float2 f1 = __half22float2(*(__half2*)&v.y);
            acc.x += wv * f0.x;
            acc.y += wv * f0.y;
            acc.z += wv * f1.x;
            acc.w += wv * f1.y;
        }
    }
    float4* s4 = (float4*)(g_xsum + (size_t)warp * 128);
    float4 sv = s4[lane];
    sv.x += acc.x; sv.y += acc.y; sv.z += acc.z; sv.w += acc.w;
    if (last) {
        float4 o;
        o.x = ALPHA * sv.x;
        o.y = ALPHA * sv.y;
        o.z = ALPHA * sv.z;
        o.w = ALPHA * sv.w;
        ((float4*)(out + (size_t)warp * 128))[lane] = o;
    } else {
        s4[lane] = sv;
        __half2 h0 = __floats2half2_rn(acc.x, acc.y);
        __half2 h1 = __floats2half2_rn(acc.z, acc.w);
        uint2 u;
        u.x = *(unsigned int*)&h0;
        u.y = *(unsigned int*)&h1;
        ((uint2*)(xout + (size_t)warp * 128))[lane] = u;
    }
}

// ---------------- launch ----------------
extern "C" void kernel_launch(void* const* d_in, const int* in_sizes, int n_in,
                              void* d_out, int out_size) {
    const int* ei = (const int*)d_in[0];
    const float* item_features = (const float*)d_in[1];
    const float* embedding = (const float*)d_in[2];
    const float* W1 = (const float*)d_in[3];
    const float* b1 = (const float*)d_in[4];
    const float* g1 = (const float*)d_in[5];
    const float* be1 = (const float*)d_in[6];
    const float* W2 = (const float*)d_in[7];
    const float* b2 = (const float*)d_in[8];
    const float* g2 = (const float*)d_in[9];
    const float* be2 = (const float*)d_in[10];
    const float* W3 = (const float*)d_in[11];
    const float* b3 = (const float*)d_in[12];
    const float* mw = (const float*)d_in[13];
    float* out = (float*)d_out;

    __nv_bfloat16* featb; cudaGetSymbolAddress((void**)&featb, g_featb);
    __nv_bfloat16* W1t; cudaGetSymbolAddress((void**)&W1t, g_W1t);
    __nv_bfloat16* W2t; cudaGetSymbolAddress((void**)&W2t, g_W2t);
    __nv_bfloat16* W3t; cudaGetSymbolAddress((void**)&W3t, g_W3t);
    float* h1; cudaGetSymbolAddress((void**)&h1, g_h1);
    __nv_bfloat16* h1b; cudaGetSymbolAddress((void**)&h1b, g_h1b);
    float* h2; cudaGetSymbolAddress((void**)&h2, g_h2);
    __nv_bfloat16* h2b; cudaGetSymbolAddress((void**)&h2b, g_h2b);
    float* h3; cudaGetSymbolAddress((void**)&h3, g_h3);
    __half* xhA; cudaGetSymbolAddress((void**)&xhA, g_xhA);
    __half* xhB; cudaGetSymbolAddress((void**)&xhB, g_xhB);

    cudaFuncSetAttribute(bgemm_bias, cudaFuncAttributeMaxDynamicSharedMemorySize,
                         GSMEM_BYTES);

    // --- GEMM1 at launch idx 3 (ncu capture slot) ---
    k_cvtA<<<(NUM_ITEMS * FEAT_DIM / 4 + 255) / 256, 256>>>(item_features);          // 0
    { dim3 g(512 / 32, FEAT_DIM / 32); k_cvtWt<<<g, dim3(32, 32)>>>(W1, W1t, FEAT_DIM, 512); } // 1
    k_zero_cnt<<<(NUM_NODES + 255) / 256, 256>>>();                                   // 2
    { dim3 grid(512 / 128, (NUM_ITEMS + 127) / 128);
      bgemm_bias<<<grid, 256, GSMEM_BYTES>>>(featb, W1t, b1, h1,
                                             NUM_ITEMS, 512, FEAT_DIM); }             // 3 <- profiled

    // CSR build (single stream; dinv fused into k_partial)
    k_count<<<(N_EDGES + 255) / 256, 256>>>(ei);
    k_partial<<<NUM_BLK, 1024>>>();
    k_scanb<<<1, 128>>>();
    k_scatter<<<NUM_BLK, 1024>>>();
    k_fill<<<(N_EDGES + 255) / 256, 256>>>(ei);

    // remaining conversions + MLP
    { dim3 g(128 / 32, 512 / 32); k_cvtWt<<<g, dim3(32, 32)>>>(W2, W2t, 512, 128); }
    { dim3 g(128 / 32, 128 / 32); k_cvtWt<<<g, dim3(32, 32)>>>(W3, W3t, 128, 128); }
    ln_relu_512<<<NUM_ITEMS, 256>>>(h1, g1, be1, h1b);
    { dim3 grid(1, (NUM_ITEMS + 127) / 128);
      bgemm_bias<<<grid, 256, GSMEM_BYTES>>>(h1b, W2t, b2, h2, NUM_ITEMS, 128, 512); }
    ln_relu_128<<<NUM_ITEMS / 2, 256>>>(h2, g2, be2, h2b);
    { dim3 grid(1, (NUM_ITEMS + 127) / 128);
      bgemm_bias<<<grid, 256, GSMEM_BYTES>>>(h2b, W3t, b3, h3, NUM_ITEMS, 128, 128); }
    k_fuse<<<NUM_ITEMS, 128>>>(embedding, mw);
    k_user<<<(NUM_USERS * HID / 4 + 255) / 256, 256>>>(embedding);

    // 3 propagation layers (fp16 gather, fp32 running sum; last writes out)
    int pblocks = (NUM_NODES * 32 + 255) / 256;
    k_prop<<<pblocks, 256>>>(xhA, xhB, out, 0);
    k_prop<<<pblocks, 256>>>(xhB, xhA, out, 0);
    k_prop<<<pblocks, 256>>>(xhA, xhB, out, 1);
}

// round 16
// speedup vs baseline: 1.1184x; 1.1184x over previous
#include <cuda_runtime.h>
#include <cuda_bf16.h>
#include <cuda_fp16.h>
#include <cstdint>

#define NUM_USERS 50000
#define NUM_ITEMS 20000
#define NUM_NODES 70000
#define FEAT_DIM 768
#define HID 128
#define N_EDGES 2000000
#define LN_EPS 1e-5f
#define ALPHA 0.25f
#define NUM_BLK 69   // ceil(70000/1024)

// bgemm tile constants
#define GSTAGES 4
#define TILE_ELEMS (128 * 40)
#define GSMEM_BYTES (GSTAGES * 2 * TILE_ELEMS * 2)   // 81920 B

// ---------------- scratch (static device globals; no allocation) ----------------
__device__ __nv_bfloat16 g_featb[(size_t)NUM_ITEMS * FEAT_DIM];
__device__ __nv_bfloat16 g_W1t[(size_t)512 * FEAT_DIM];   // [N=512][K=768]
__device__ __nv_bfloat16 g_W2t[(size_t)128 * 512];        // [N=128][K=512]
__device__ __nv_bfloat16 g_W3t[(size_t)128 * 128];        // [N=128][K=128]
__device__ float g_h1[(size_t)NUM_ITEMS * 512];
__device__ __nv_bfloat16 g_h1b[(size_t)NUM_ITEMS * 512];
__device__ float g_h2[(size_t)NUM_ITEMS * HID];
__device__ __nv_bfloat16 g_h2b[(size_t)NUM_ITEMS * HID];
__device__ float g_h3[(size_t)NUM_ITEMS * HID];
__device__ float g_xsum[(size_t)NUM_NODES * HID];          // running fp32 sum
__device__ __align__(16) __half g_xhA[(size_t)NUM_NODES * HID];  // fp16 ping
__device__ __align__(16) __half g_xhB[(size_t)NUM_NODES * HID];  // fp16 pong
__device__ int   g_cnt[NUM_NODES];
__device__ float g_dinv[NUM_NODES];
__device__ int   g_rowptr[NUM_NODES + 1];
__device__ int   g_cursor[NUM_NODES];
__device__ int2  g_cw[N_EDGES];                            // fused (col, w-bits)
__device__ int   g_bsum[NUM_BLK];
__device__ int   g_boff[128];

// ---------------- cp.async helpers ----------------
__device__ __forceinline__ void cp16(void* smem_dst, const void* gsrc, bool pred) {
    uint32_t d = (uint32_t)__cvta_generic_to_shared(smem_dst);
    int sz = pred ? 16 : 0;
    asm volatile("cp.async.cg.shared.global [%0], [%1], 16, %2;\n"
                 :: "r"(d), "l"(gsrc), "r"(sz));
}
__device__ __forceinline__ void cp_commit() {
    asm volatile("cp.async.commit_group;\n");
}
template <int N>
__device__ __forceinline__ void cp_wait() {
    asm volatile("cp.async.wait_group %0;\n" :: "n"(N));
}

// ---------------- CSR build ----------------
__global__ void k_zero_cnt() {
    int i = blockIdx.x * blockDim.x + threadIdx.x;
    if (i < NUM_NODES) g_cnt[i] = 0;
}

__global__ void k_count(const int* __restrict__ ei) {
    int e = blockIdx.x * blockDim.x + threadIdx.x;
    if (e < N_EDGES) atomicAdd(&g_cnt[ei[N_EDGES + e]], 1);
}

// partial block sums for the scan + dinv (fused: both only need g_cnt)
__global__ void k_partial() {
    __shared__ int sh[32];
    int tid = threadIdx.x;
    int i = blockIdx.x * 1024 + tid;
    int c = 0;
    if (i < NUM_NODES) {
        c = g_cnt[i];
        g_dinv[i] = (c > 0) ? rsqrtf((float)c) : 0.0f;
    }
    int s = c;
#pragma unroll
    for (int o = 16; o > 0; o >>= 1) s += __shfl_down_sync(0xffffffffu, s, o);
    if ((tid & 31) == 0) sh[tid >> 5] = s;
    __syncthreads();
    if (tid < 32) {
        int v = sh[tid];
#pragma unroll
        for (int o = 16; o > 0; o >>= 1) v += __shfl_down_sync(0xffffffffu, v, o);
        if (tid == 0) g_bsum[blockIdx.x] = v;
    }
}

__global__ void k_scanb() {
    __shared__ int s[128];
    int tid = threadIdx.x;
    int v = (tid < NUM_BLK) ? g_bsum[tid] : 0;
    s[tid] = v;
    __syncthreads();
    for (int off = 1; off < 128; off <<= 1) {
        int add = 0;
        if (tid >= off) add = s[tid - off];
        __syncthreads();
        if (tid >= off) s[tid] += add;
        __syncthreads();
    }
    g_boff[tid] = s[tid] - v;
}

__global__ void k_scatter() {
    __shared__ int s[1024];
    int tid = threadIdx.x;
    int i = blockIdx.x * 1024 + tid;
    int c = (i < NUM_NODES) ? g_cnt[i] : 0;
    s[tid] = c;
    __syncthreads();
    for (int off = 1; off < 1024; off <<= 1) {
        int add = 0;
        if (tid >= off) add = s[tid - off];
        __syncthreads();
        if (tid >= off) s[tid] += add;
        __syncthreads();
    }
    if (i < NUM_NODES) {
        int p = g_boff[blockIdx.x] + s[tid] - c;
        g_rowptr[i] = p;
        g_cursor[i] = p;
    }
    if (i == NUM_NODES - 1) g_rowptr[NUM_NODES] = N_EDGES;
}

__global__ void k_fill(const int* __restrict__ ei) {
    int e = blockIdx.x * blockDim.x + threadIdx.x;
    if (e < N_EDGES) {
        int s = ei[e];
        int d = ei[N_EDGES + e];
        int pos = atomicAdd(&g_cursor[d], 1);
        float w = g_dinv[s] * g_dinv[d];
        g_cw[pos] = make_int2(s, __float_as_int(w));
    }
}

// ---------------- conversions ----------------
__global__ void k_cvtA(const float* __restrict__ A) {
    int i = blockIdx.x * blockDim.x + threadIdx.x;
    const int total = NUM_ITEMS * FEAT_DIM / 4;
    if (i < total) {
        float4 v = ((const float4*)A)[i];
        __nv_bfloat162 p0 = __floats2bfloat162_rn(v.x, v.y);
        __nv_bfloat162 p1 = __floats2bfloat162_rn(v.z, v.w);
        uint2 u;
        u.x = *(unsigned int*)&p0;
        u.y = *(unsigned int*)&p1;
        ((uint2*)g_featb)[i] = u;
    }
}

__global__ void k_cvtWt(const float* __restrict__ W, __nv_bfloat16* __restrict__ Wt,
                        int K, int N) {
    __shared__ float sh[32][33];
    int k0 = blockIdx.y * 32, n0 = blockIdx.x * 32;
    int tx = threadIdx.x, ty = threadIdx.y;
    sh[ty][tx] = W[(size_t)(k0 + ty) * N + n0 + tx];
    __syncthreads();
    Wt[(size_t)(n0 + ty) * K + k0 + tx] = __float2bfloat16_rn(sh[tx][ty]);
}

// ---------------- bf16 tensor-core GEMM: 4-stage cp.async, 1 sync/iter, ldmatrix ----
// C = A @ Bt^T + bias.  A: [M][K] bf16, Bt: [N][K] bf16, C fp32 [M][N].
// BM=128, BN=128, BK=32.  256 threads, 8 warps as 4(m) x 2(n), warp tile 32x64.
// NO minblocks hint: 98 regs / 2 CTAs per SM is the validated operating point.
__global__ __launch_bounds__(256) void bgemm_bias(
    const __nv_bfloat16* __restrict__ A, const __nv_bfloat16* __restrict__ Bt,
    const float* __restrict__ bias, float* __restrict__ C, int M, int N, int K) {
    extern __shared__ __nv_bfloat16 sdyn[];
    __nv_bfloat16* Asb = sdyn;
    __nv_bfloat16* Bsb = sdyn + GSTAGES * TILE_ELEMS;
    int tid = threadIdx.x;
    int warp = tid >> 5, lane = tid & 31;
    int wm = (warp >> 1) * 32;
    int wn = (warp & 1) * 64;
    int bm = blockIdx.y * 128, bn = blockIdx.x * 128;
    int g = lane >> 2, tc = lane & 3;
    int lrow = lane & 7, lsel = lane >> 3;      // ldmatrix addressing

    float acc[2][8][4];
#pragma unroll
    for (int a = 0; a < 2; a++)
#pragma unroll
        for (int b = 0; b < 8; b++)
#pragma unroll
            for (int c = 0; c < 4; c++) acc[a][b][c] = 0.f;

    const int KT = K / 32;

    auto load_stage = [&](int k0, int s) {
        __nv_bfloat16* As = Asb + s * TILE_ELEMS;
        __nv_bfloat16* Bs = Bsb + s * TILE_ELEMS;
#pragma unroll
        for (int i = 0; i < 2; i++) {
            int c = tid + i * 256;
            int m = c >> 2;
            int kq = (c & 3) * 8;
            cp16(As + m * 40 + kq, A + (size_t)(bm + m) * K + k0 + kq, bm + m < M);
        }
#pragma unroll
        for (int i = 0; i < 2; i++) {
            int c = tid + i * 256;
            int n = c >> 2;
            int kq = (c & 3) * 8;
            cp16(Bs + n * 40 + kq, Bt + (size_t)(bn + n) * K + k0 + kq, true);
        }
    };

    // prologue: stages 0,1,2 in flight (empty groups still committed to keep count)
    load_stage(0, 0);
    cp_commit();
    if (KT > 1) load_stage(32, 1);
    cp_commit();
    if (KT > 2) load_stage(64, 2);
    cp_commit();

    int st = 0;
    for (int it = 0; it < KT; it++) {
        cp_wait<2>();          // group carrying stage st has completed
        __syncthreads();       // all warps done with compute(it-1)
        uint32_t asb = (uint32_t)__cvta_generic_to_shared(Asb + st * TILE_ELEMS);
        uint32_t bsb = (uint32_t)__cvta_generic_to_shared(Bsb + st * TILE_ELEMS);
#pragma unroll
        for (int ks = 0; ks < 2; ks++) {
            int kb = ks * 16;
            uint32_t af[2][4], bf[8][2];
#pragma unroll
            for (int mt = 0; mt < 2; mt++) {
                int row = wm + mt * 16 + lrow + ((lsel & 1) << 3);
                int col = kb + ((lsel >> 1) << 3);
                uint32_t addr = asb + (uint32_t)(row * 40 + col) * 2;
                asm volatile(
                    "ldmatrix.sync.aligned.m8n8.x4.shared.b16 {%0,%1,%2,%3}, [%4];\n"
                    : "=r"(af[mt][0]), "=r"(af[mt][1]), "=r"(af[mt][2]), "=r"(af[mt][3])
                    : "r"(addr));
            }
#pragma unroll
            for (int p = 0; p < 4; p++) {
                int row = wn + p * 16 + ((lsel >> 1) << 3) + lrow;
                int col = kb + ((lsel & 1) << 3);
                uint32_t addr = bsb + (uint32_t)(row * 40 + col) * 2;
                asm volatile(
                    "ldmatrix.sync.aligned.m8n8.x4.shared.b16 {%0,%1,%2,%3}, [%4];\n"
                    : "=r"(bf[2 * p][0]), "=r"(bf[2 * p][1]),
                      "=r"(bf[2 * p + 1][0]), "=r"(bf[2 * p + 1][1])
                    : "r"(addr));
            }
#pragma unroll
            for (int mt = 0; mt < 2; mt++)
#pragma unroll
                for (int nt = 0; nt < 8; nt++) {
                    asm volatile(
                        "mma.sync.aligned.m16n8k16.row.col.f32.bf16.bf16.f32 "
                        "{%0,%1,%2,%3}, {%4,%5,%6,%7}, {%8,%9}, {%0,%1,%2,%3};\n"
                        : "+f"(acc[mt][nt][0]), "+f"(acc[mt][nt][1]),
                          "+f"(acc[mt][nt][2]), "+f"(acc[mt][nt][3])
                        : "r"(af[mt][0]), "r"(af[mt][1]), "r"(af[mt][2]), "r"(af[mt][3]),
                          "r"(bf[nt][0]), "r"(bf[nt][1]));
                }
        }
        // refill stage consumed at it-1 (sync above ordered all its readers)
        if (it + 3 < KT) {
            int ns = st + 3;
            if (ns >= GSTAGES) ns -= GSTAGES;
            load_stage((it + 3) * 32, ns);
        }
        cp_commit();
        if (++st == GSTAGES) st = 0;
    }
#pragma unroll
    for (int mt = 0; mt < 2; mt++) {
        int r0 = bm + wm + mt * 16 + g;
#pragma unroll
        for (int nt = 0; nt < 8; nt++) {
            int col = bn + wn + nt * 8 + 2 * tc;
            float bx = bias[col], by = bias[col + 1];
            if (r0 < M) {
                float2 v0 = make_float2(acc[mt][nt][0] + bx, acc[mt][nt][1] + by);
                *(float2*)(C + (size_t)r0 * N + col) = v0;
            }
            if (r0 + 8 < M) {
                float2 v1 = make_float2(acc[mt][nt][2] + bx, acc[mt][nt][3] + by);
                *(float2*)(C + (size_t)(r0 + 8) * N + col) = v1;
            }
        }
    }
}

// ---------------- LayerNorm + ReLU (fp32 in, bf16 out) ----------------
__global__ void ln_relu_512(const float* __restrict__ h, const float* __restrict__ g,
                            const float* __restrict__ be, __nv_bfloat16* __restrict__ hb) {
    __shared__ float sh1[8], sh2[8];
    int row = blockIdx.x;
    int tid = threadIdx.x;
    const float* r = h + (size_t)row * 512;
    float a = r[tid], b = r[tid + 256];
    float s = a + b, q = a * a + b * b;
#pragma unroll
    for (int o = 16; o > 0; o >>= 1) {
        s += __shfl_down_sync(0xffffffffu, s, o);
        q += __shfl_down_sync(0xffffffffu, q, o);
    }
    if ((tid & 31) == 0) { sh1[tid >> 5] = s; sh2[tid >> 5] = q; }
    __syncthreads();
    if (tid < 8) {
        s = sh1[tid]; q = sh2[tid];
#pragma unroll
        for (int o = 4; o > 0; o >>= 1) {
            s += __shfl_down_sync(0xffu, s, o);
            q += __shfl_down_sync(0xffu, q, o);
        }
        if (tid == 0) { sh1[0] = s; sh2[0] = q; }
    }
    __syncthreads();
    float mu = sh1[0] * (1.f / 512.f);
    float var = sh2[0] * (1.f / 512.f) - mu * mu;
    float inv = rsqrtf(var + LN_EPS);
    __nv_bfloat16* o = hb + (size_t)row * 512;
    o[tid] = __float2bfloat16_rn(fmaxf((a - mu) * inv * g[tid] + be[tid], 0.f));
    o[tid + 256] = __float2bfloat16_rn(fmaxf((b - mu) * inv * g[tid + 256] + be[tid + 256], 0.f));
}

// 2 rows per block (128 cols each)
__global__ void ln_relu_128(const float* __restrict__ h, const float* __restrict__ g,
                            const float* __restrict__ be, __nv_bfloat16* __restrict__ hb) {
    __shared__ float sh1[2][4], sh2[2][4];
    int half = threadIdx.x >> 7;
    int tid = threadIdx.x & 127;
    int row = blockIdx.x * 2 + half;
    const float* r = h + (size_t)row * 128;
    float a = r[tid];
    float s = a, q = a * a;
#pragma unroll
    for (int o = 16; o > 0; o >>= 1) {
        s += __shfl_down_sync(0xffffffffu, s, o);
        q += __shfl_down_sync(0xffffffffu, q, o);
    }
    if ((tid & 31) == 0) { sh1[half][tid >> 5] = s; sh2[half][tid >> 5] = q; }
    __syncthreads();
    float ts = sh1[half][0] + sh1[half][1] + sh1[half][2] + sh1[half][3];
    float tq = sh2[half][0] + sh2[half][1] + sh2[half][2] + sh2[half][3];
    float mu = ts * (1.f / 128.f);
    float var = tq * (1.f / 128.f) - mu * mu;
    float inv = rsqrtf(var + LN_EPS);
    hb[(size_t)row * 128 + tid] =
        __float2bfloat16_rn(fmaxf((a - mu) * inv * g[tid] + be[tid], 0.f));
}

// ---------------- fuse + user init: xsum = x0 (fp32), xhA = x0 (fp16) ----------------
__global__ void k_fuse(const float* __restrict__ emb, const float* __restrict__ mw) {
    __shared__ float sh[4];
    int row = blockIdx.x;
    int tid = threadIdx.x;
    float v = g_h3[(size_t)row * 128 + tid];
    float q = v * v;
#pragma unroll
    for (int o = 16; o > 0; o >>= 1) q += __shfl_down_sync(0xffffffffu, q, o);
    if ((tid & 31) == 0) sh[tid >> 5] = q;
    __syncthreads();
    if (tid == 0) sh[0] = sh[0] + sh[1] + sh[2] + sh[3];
    __syncthreads();
    float denom = fmaxf(sqrtf(sh[0]), 1e-12f);
    size_t gi = (size_t)(NUM_USERS + row) * 128 + tid;
    float e = emb[gi] + mw[0] * (v / denom);
    g_xsum[gi] = e;
    g_xhA[gi] = __float2half(e);
}

__global__ void k_user(const float* __restrict__ emb) {
    int i = blockIdx.x * blockDim.x + threadIdx.x;   // NUM_USERS*128/4 float4s
    const int total = NUM_USERS * HID / 4;
    if (i < total) {
        float4 v = ((const float4*)emb)[i];
        ((float4*)g_xsum)[i] = v;
        __half2 h0 = __floats2half2_rn(v.x, v.y);
        __half2 h1 = __floats2half2_rn(v.z, v.w);
        uint2 u;
        u.x = *(unsigned int*)&h0;
        u.y = *(unsigned int*)&h1;
        ((uint2*)g_xhA)[i] = u;
    }
}

// ---------------- pull-based propagation (fp16 gather, fp32 accumulate) ----------
// known-good shape: one warp per dst node, shfl staging, unroll 8.
__global__ void k_prop(const __half* __restrict__ xin, __half* __restrict__ xout,
                       float* __restrict__ out, int last) {
    int warp = (blockIdx.x * blockDim.x + threadIdx.x) >> 5;
    int lane = threadIdx.x & 31;
    if (warp >= NUM_NODES) return;
    int beg = g_rowptr[warp];
    int end = g_rowptr[warp + 1];
    float4 acc = make_float4(0.f, 0.f, 0.f, 0.f);
    int j = beg;
    for (; j + 32 <= end; j += 32) {
        int2 cw = g_cw[j + lane];
        int myc = cw.x;
        float myw = __int_as_float(cw.y);
#pragma unroll 8
        for (int k = 0; k < 32; k++) {
            int s = __shfl_sync(0xffffffffu, myc, k);
            float wv = __shfl_sync(0xffffffffu, myw, k);
            uint2 v = ((const uint2*)(xin + (size_t)s * 128))[lane];
            float2 f0 = __half22float2(*(__half2*)&v.x);
            float2 f1 = __half22float2(*(__half2*)&v.y);
            acc.x += wv * f0.x;
            acc.y += wv * f0.y;
            acc.z += wv * f1.x;
            acc.w += wv * f1.y;
        }
    }
    int n = end - j;
    if (n > 0) {
        int myc = 0;
        float myw = 0.f;
        if (lane < n) {
            int2 cw = g_cw[j + lane];
            myc = cw.x;
            myw = __int_as_float(cw.y);
        }
#pragma unroll 4
        for (int k = 0; k < n; k++) {
            int s = __shfl_sync(0xffffffffu, myc, k);
            float wv = __shfl_sync(0xffffffffu, myw, k);
            uint2 v = ((const uint2*)(xin + (size_t)s * 128))[lane];
            float2 f0 = __half22float2(*(__half2*)&v.x);
            float2 f1 = __half22float2(*(__half2*)&v.y);
            acc.x += wv * f0.x;
            acc.y += wv * f0.y;
            acc.z += wv * f1.x;
            acc.w += wv * f1.y;
        }
    }
    float4* s4 = (float4*)(g_xsum + (size_t)warp * 128);
    float4 sv = s4[lane];
    sv.x += acc.x; sv.y += acc.y; sv.z += acc.z; sv.w += acc.w;
    if (last) {
        float4 o;
        o.x = ALPHA * sv.x;
        o.y = ALPHA * sv.y;
        o.z = ALPHA * sv.z;
        o.w = ALPHA * sv.w;
        ((float4*)(out + (size_t)warp * 128))[lane] = o;
    } else {
        s4[lane] = sv;
        __half2 h0 = __floats2half2_rn(acc.x, acc.y);
        __half2 h1 = __floats2half2_rn(acc.z, acc.w);
        uint2 u;
        u.x = *(unsigned int*)&h0;
        u.y = *(unsigned int*)&h1;
        ((uint2*)(xout + (size_t)warp * 128))[lane] = u;
    }
}

// ---------------- launch ----------------
extern "C" void kernel_launch(void* const* d_in, const int* in_sizes, int n_in,
                              void* d_out, int out_size) {
    const int* ei = (const int*)d_in[0];
    const float* item_features = (const float*)d_in[1];
    const float* embedding = (const float*)d_in[2];
    const float* W1 = (const float*)d_in[3];
    const float* b1 = (const float*)d_in[4];
    const float* g1 = (const float*)d_in[5];
    const float* be1 = (const float*)d_in[6];
    const float* W2 = (const float*)d_in[7];
    const float* b2 = (const float*)d_in[8];
    const float* g2 = (const float*)d_in[9];
    const float* be2 = (const float*)d_in[10];
    const float* W3 = (const float*)d_in[11];
    const float* b3 = (const float*)d_in[12];
    const float* mw = (const float*)d_in[13];
    float* out = (float*)d_out;

    __nv_bfloat16* featb; cudaGetSymbolAddress((void**)&featb, g_featb);
    __nv_bfloat16* W1t; cudaGetSymbolAddress((void**)&W1t, g_W1t);
    __nv_bfloat16* W2t; cudaGetSymbolAddress((void**)&W2t, g_W2t);
    __nv_bfloat16* W3t; cudaGetSymbolAddress((void**)&W3t, g_W3t);
    float* h1; cudaGetSymbolAddress((void**)&h1, g_h1);
    __nv_bfloat16* h1b; cudaGetSymbolAddress((void**)&h1b, g_h1b);
    float* h2; cudaGetSymbolAddress((void**)&h2, g_h2);
    __nv_bfloat16* h2b; cudaGetSymbolAddress((void**)&h2b, g_h2b);
    float* h3; cudaGetSymbolAddress((void**)&h3, g_h3);
    __half* xhA; cudaGetSymbolAddress((void**)&xhA, g_xhA);
    __half* xhB; cudaGetSymbolAddress((void**)&xhB, g_xhB);

    cudaFuncSetAttribute(bgemm_bias, cudaFuncAttributeMaxDynamicSharedMemorySize,
                         GSMEM_BYTES);

    // --- GEMM1 at launch idx 3 (ncu capture slot) ---
    k_cvtA<<<(NUM_ITEMS * FEAT_DIM / 4 + 255) / 256, 256>>>(item_features);          // 0
    { dim3 g(512 / 32, FEAT_DIM / 32); k_cvtWt<<<g, dim3(32, 32)>>>(W1, W1t, FEAT_DIM, 512); } // 1
    k_zero_cnt<<<(NUM_NODES + 255) / 256, 256>>>();                                   // 2
    { dim3 grid(512 / 128, (NUM_ITEMS + 127) / 128);
      bgemm_bias<<<grid, 256, GSMEM_BYTES>>>(featb, W1t, b1, h1,
                                             NUM_ITEMS, 512, FEAT_DIM); }             // 3 <- profiled

    // CSR build (single stream; dinv fused into k_partial)
    k_count<<<(N_EDGES + 255) / 256, 256>>>(ei);
    k_partial<<<NUM_BLK, 1024>>>();
    k_scanb<<<1, 128>>>();
    k_scatter<<<NUM_BLK, 1024>>>();
    k_fill<<<(N_EDGES + 255) / 256, 256>>>(ei);

    // remaining conversions + MLP
    { dim3 g(128 / 32, 512 / 32); k_cvtWt<<<g, dim3(32, 32)>>>(W2, W2t, 512, 128); }
    { dim3 g(128 / 32, 128 / 32); k_cvtWt<<<g, dim3(32, 32)>>>(W3, W3t, 128, 128); }
    ln_relu_512<<<NUM_ITEMS, 256>>>(h1, g1, be1, h1b);
    { dim3 grid(1, (NUM_ITEMS + 127) / 128);
      bgemm_bias<<<grid, 256, GSMEM_BYTES>>>(h1b, W2t, b2, h2, NUM_ITEMS, 128, 512); }
    ln_relu_128<<<NUM_ITEMS / 2, 256>>>(h2, g2, be2, h2b);
    { dim3 grid(1, (NUM_ITEMS + 127) / 128);
      bgemm_bias<<<grid, 256, GSMEM_BYTES>>>(h2b, W3t, b3, h3, NUM_ITEMS, 128, 128); }
    k_fuse<<<NUM_ITEMS, 128>>>(embedding, mw);
    k_user<<<(NUM_USERS * HID / 4 + 255) / 256, 256>>>(embedding);

    // 3 propagation layers (fp16 gather, fp32 running sum; last writes out)
    int pblocks = (NUM_NODES * 32 + 255) / 256;
    k_prop<<<pblocks, 256>>>(xhA, xhB, out, 0);
    k_prop<<<pblocks, 256>>>(xhB, xhA, out, 0);
    k_prop<<<pblocks, 256>>>(xhA, xhB, out, 1);
}